// round 3
// baseline (speedup 1.0000x reference)
#include <cuda_runtime.h>
#include <cuda_bf16.h>

// ---------------------------------------------------------------------------
// GATv2 (2 layers) + BN + ELU + linear classifier.
// Shapes fixed by the problem: N=50000, E=800000, IN=128, H=8, C=32, NC=2.
// ---------------------------------------------------------------------------

#define NMAX 50000
#define EMAX 800000
#define H_ 8
#define C_ 32
#define HC_ 256       // H*C
#define ETOTMAX (EMAX + NMAX)
#define EPS_ 1e-5f
#define SLOPE_ 0.2f

// ------------------------- static device scratch ---------------------------
__device__ float    g_xl[(size_t)NMAX * HC_];
__device__ float    g_xr[(size_t)NMAX * HC_];
__device__ float    g_h [(size_t)NMAX * HC_];
__device__ float    g_acc[(size_t)NMAX * HC_];
__device__ float    g_elog[(size_t)ETOTMAX * H_];
__device__ unsigned g_nmax[(size_t)NMAX * H_];
__device__ float    g_den [(size_t)NMAX * H_];
__device__ int      g_src[EMAX];
__device__ int      g_dst[EMAX];
__device__ int      g_is64;

// ------------------------- helpers -----------------------------------------
__device__ __forceinline__ unsigned f2u_mono(float f) {
    unsigned u = __float_as_uint(f);
    return (u & 0x80000000u) ? ~u : (u | 0x80000000u);
}
__device__ __forceinline__ float u2f_mono(unsigned u) {
    u = (u & 0x80000000u) ? (u & 0x7fffffffu) : ~u;
    return __uint_as_float(u);
}
__device__ __forceinline__ void red_add_v4(float* addr, float4 v) {
    asm volatile("red.global.add.v4.f32 [%0], {%1, %2, %3, %4};"
                 :: "l"(addr), "f"(v.x), "f"(v.y), "f"(v.z), "f"(v.w)
                 : "memory");
}

// ------------------------- edge index conversion ----------------------------
__global__ void k_detect(const int* __restrict__ ei, int E) {
    // If data is int64 (values < 2^31), every odd 32-bit word is 0.
    int ok64 = 1;
    int limit = (E > 64) ? 64 : E;
    for (int i = 0; i < limit; i++) {
        if (ei[2 * i + 1] != 0) { ok64 = 0; break; }
    }
    g_is64 = ok64;
}

__global__ void k_convert(const void* __restrict__ ei, int E) {
    int i = blockIdx.x * blockDim.x + threadIdx.x;
    int tot = 2 * E;
    if (i >= tot) return;
    int v;
    if (g_is64) v = (int)((const long long*)ei)[i];
    else        v = ((const int*)ei)[i];
    if (i < E) g_src[i] = v;
    else       g_dst[i - E] = v;
}

// ------------------------- SGEMM: C[M,Nn] = A[M,K] @ B[K,Nn] ----------------
// Nn multiple of 64, K multiple of 16. 64x64 tile, 4x4 per thread, 256 thr.
__global__ void sgemm64(const float* __restrict__ A, const float* __restrict__ B,
                        float* __restrict__ Cc, int M, int K, int Nn) {
    __shared__ float As[16][64];
    __shared__ float Bs[16][68];
    int bm = blockIdx.y, bn = blockIdx.x;
    int t  = threadIdx.x;
    int tx = t & 15, ty = t >> 4;
    int row0 = bm * 64, col0 = bn * 64;
    float acc[4][4] = {};
    for (int k0 = 0; k0 < K; k0 += 16) {
#pragma unroll
        for (int i = 0; i < 4; i++) {
            int idx = t + i * 256;            // 0..1023
            int m = idx >> 4;                 // row in tile
            int kk = idx & 15;
            int gr = row0 + m;
            As[kk][m] = (gr < M) ? A[(long long)gr * K + k0 + kk] : 0.f;
        }
#pragma unroll
        for (int i = 0; i < 4; i++) {
            int idx = t + i * 256;
            int kk = idx >> 6;
            int n = idx & 63;
            Bs[kk][n] = B[(long long)(k0 + kk) * Nn + col0 + n];
        }
        __syncthreads();
#pragma unroll
        for (int kk = 0; kk < 16; kk++) {
            float a[4], b[4];
#pragma unroll
            for (int i = 0; i < 4; i++) a[i] = As[kk][ty * 4 + i];
#pragma unroll
            for (int j = 0; j < 4; j++) b[j] = Bs[kk][tx * 4 + j];
#pragma unroll
            for (int i = 0; i < 4; i++)
#pragma unroll
                for (int j = 0; j < 4; j++) acc[i][j] += a[i] * b[j];
        }
        __syncthreads();
    }
#pragma unroll
    for (int i = 0; i < 4; i++) {
        int gr = row0 + ty * 4 + i;
        if (gr < M) {
#pragma unroll
            for (int j = 0; j < 4; j++)
                Cc[(long long)gr * Nn + col0 + tx * 4 + j] = acc[i][j];
        }
    }
}

// ------------------------- edge pass A: logits + segment max ----------------
// Warp per edge; float4 gathers. Float4 index f covers head f>>3.
// Lane handles float4 indices lane (head lane>>3) and lane+32 (head +4).
__global__ void edge_logits_max(const float* __restrict__ att, int E, int N) {
    int Etot = E + N;
    int lane = threadIdx.x & 31;
    int warp = (blockIdx.x * blockDim.x + threadIdx.x) >> 5;
    int nwarp = (gridDim.x * blockDim.x) >> 5;
    const float4* att4 = (const float4*)att;
    float4 a0 = att4[lane];
    float4 a1 = att4[lane + 32];
    for (int e = warp; e < Etot; e += nwarp) {
        int s, d;
        if (e < E) { s = g_src[e]; d = g_dst[e]; }
        else       { s = e - E; d = s; }
        const float4* pl4 = (const float4*)(g_xl + (long long)s * HC_);
        const float4* pr4 = (const float4*)(g_xr + (long long)d * HC_);
        float4 l0 = pl4[lane],      r0 = pr4[lane];
        float4 l1 = pl4[lane + 32], r1 = pr4[lane + 32];
        float v, s0 = 0.f, s1 = 0.f;
        v = l0.x + r0.x; v = (v > 0.f) ? v : SLOPE_ * v; s0 += v * a0.x;
        v = l0.y + r0.y; v = (v > 0.f) ? v : SLOPE_ * v; s0 += v * a0.y;
        v = l0.z + r0.z; v = (v > 0.f) ? v : SLOPE_ * v; s0 += v * a0.z;
        v = l0.w + r0.w; v = (v > 0.f) ? v : SLOPE_ * v; s0 += v * a0.w;
        v = l1.x + r1.x; v = (v > 0.f) ? v : SLOPE_ * v; s1 += v * a1.x;
        v = l1.y + r1.y; v = (v > 0.f) ? v : SLOPE_ * v; s1 += v * a1.y;
        v = l1.z + r1.z; v = (v > 0.f) ? v : SLOPE_ * v; s1 += v * a1.z;
        v = l1.w + r1.w; v = (v > 0.f) ? v : SLOPE_ * v; s1 += v * a1.w;
        // reduce over the 8 lanes sharing a head (lanes differing in low 3 bits)
#pragma unroll
        for (int off = 4; off; off >>= 1) {
            s0 += __shfl_xor_sync(0xffffffffu, s0, off);
            s1 += __shfl_xor_sync(0xffffffffu, s1, off);
        }
        if ((lane & 7) == 0) {
            int h = lane >> 3;
            g_elog[(long long)e * H_ + h]     = s0;
            g_elog[(long long)e * H_ + h + 4] = s1;
            atomicMax(&g_nmax[d * H_ + h],     f2u_mono(s0));
            atomicMax(&g_nmax[d * H_ + h + 4], f2u_mono(s1));
        }
    }
}

// ------------------------- edge pass B: exp + segment sum -------------------
__global__ void edge_exp_sum(int E, int N) {
    int Etot = E + N;
    int e = blockIdx.x * blockDim.x + threadIdx.x;
    if (e >= Etot) return;
    int d = (e < E) ? g_dst[e] : e - E;
    const uint4* pm = (const uint4*)(g_nmax + d * H_);
    float4* pe = (float4*)(g_elog + (long long)e * H_);
    float4 ex0, ex1;
    {
        uint4 mu = pm[0]; float4 lg = pe[0];
        ex0.x = expf(lg.x - u2f_mono(mu.x));
        ex0.y = expf(lg.y - u2f_mono(mu.y));
        ex0.z = expf(lg.z - u2f_mono(mu.z));
        ex0.w = expf(lg.w - u2f_mono(mu.w));
    }
    {
        uint4 mu = pm[1]; float4 lg = pe[1];
        ex1.x = expf(lg.x - u2f_mono(mu.x));
        ex1.y = expf(lg.y - u2f_mono(mu.y));
        ex1.z = expf(lg.z - u2f_mono(mu.z));
        ex1.w = expf(lg.w - u2f_mono(mu.w));
    }
    pe[0] = ex0;
    pe[1] = ex1;
    red_add_v4(g_den + d * H_,     ex0);
    red_add_v4(g_den + d * H_ + 4, ex1);
}

// ------------------------- edge pass C: weighted aggregate ------------------
// Warp per edge, float4 loads + red.global.add.v4.f32 scatters.
__global__ void edge_aggregate(int E, int N) {
    int Etot = E + N;
    int lane = threadIdx.x & 31;
    int warp = (blockIdx.x * blockDim.x + threadIdx.x) >> 5;
    int nwarp = (gridDim.x * blockDim.x) >> 5;
    int h0 = lane >> 3, h1 = h0 + 4;
    for (int e = warp; e < Etot; e += nwarp) {
        int s, d;
        if (e < E) { s = g_src[e]; d = g_dst[e]; }
        else       { s = e - E; d = s; }
        // lanes 0..7 compute alpha for their head, then broadcast
        float al = 0.f;
        if (lane < H_)
            al = g_elog[(long long)e * H_ + lane] / g_den[d * H_ + lane];
        float a0 = __shfl_sync(0xffffffffu, al, h0);
        float a1 = __shfl_sync(0xffffffffu, al, h1);
        const float4* pl4 = (const float4*)(g_xl + (long long)s * HC_);
        float* po = g_acc + (long long)d * HC_;
        float4 x0 = pl4[lane];
        float4 x1 = pl4[lane + 32];
        float4 m0 = make_float4(a0 * x0.x, a0 * x0.y, a0 * x0.z, a0 * x0.w);
        float4 m1 = make_float4(a1 * x1.x, a1 * x1.y, a1 * x1.z, a1 * x1.w);
        red_add_v4(po + lane * 4,        m0);
        red_add_v4(po + (lane + 32) * 4, m1);
    }
}

// ------------------------- node epilogue layer 0 ----------------------------
// h = elu( bn( acc + b0 ) )   [concat: H*C features]
__global__ void node_post0(const float* __restrict__ b0, const float* __restrict__ g0,
                           const float* __restrict__ be0, const float* __restrict__ m0,
                           const float* __restrict__ v0, int N) {
    long long idx = (long long)blockIdx.x * 256 + threadIdx.x;
    if (idx >= (long long)N * HC_) return;
    int c = threadIdx.x;  // blockDim = 256 = HC_
    float x = g_acc[idx] + b0[c];
    x = (x - m0[c]) * rsqrtf(v0[c] + EPS_) * g0[c] + be0[c];
    g_h[idx] = (x > 0.f) ? x : (expf(x) - 1.f);
}

// ------------------------- node epilogue layer 1 + classifier ---------------
// y = bn( mean_h(acc) + b1 ) @ Wc + bc     (no ELU)
__global__ void node_post1(const float* __restrict__ b1, const float* __restrict__ g1,
                           const float* __restrict__ be1, const float* __restrict__ m1,
                           const float* __restrict__ v1, const float* __restrict__ Wc,
                           const float* __restrict__ bc, float* __restrict__ out, int N) {
    int lane = threadIdx.x & 31;
    int n = (blockIdx.x * blockDim.x + threadIdx.x) >> 5;
    if (n >= N) return;
    const float* pa = g_acc + (long long)n * HC_;
    float s = 0.f;
#pragma unroll
    for (int h = 0; h < H_; h++) s += pa[h * 32 + lane];
    s = s * (1.f / H_) + b1[lane];
    s = (s - m1[lane]) * rsqrtf(v1[lane] + EPS_) * g1[lane] + be1[lane];
    float y0 = s * Wc[lane * 2 + 0];
    float y1 = s * Wc[lane * 2 + 1];
#pragma unroll
    for (int off = 16; off; off >>= 1) {
        y0 += __shfl_xor_sync(0xffffffffu, y0, off);
        y1 += __shfl_xor_sync(0xffffffffu, y1, off);
    }
    if (lane == 0) {
        out[(long long)n * 2 + 0] = y0 + bc[0];
        out[(long long)n * 2 + 1] = y1 + bc[1];
    }
}

// ---------------------------------------------------------------------------
extern "C" void kernel_launch(void* const* d_in, const int* in_sizes, int n_in,
                              void* d_out, int out_size) {
    const float* x    = (const float*)d_in[0];
    const void*  ei   = d_in[1];
    const float* Wl0  = (const float*)d_in[2];
    const float* Wr0  = (const float*)d_in[3];
    const float* att0 = (const float*)d_in[4];
    const float* b0   = (const float*)d_in[5];
    const float* g0   = (const float*)d_in[6];
    const float* be0  = (const float*)d_in[7];
    const float* m0   = (const float*)d_in[8];
    const float* v0   = (const float*)d_in[9];
    const float* Wl1  = (const float*)d_in[10];
    const float* Wr1  = (const float*)d_in[11];
    const float* att1 = (const float*)d_in[12];
    const float* b1   = (const float*)d_in[13];
    const float* g1   = (const float*)d_in[14];
    const float* be1  = (const float*)d_in[15];
    const float* m1   = (const float*)d_in[16];
    const float* v1   = (const float*)d_in[17];
    const float* Wc   = (const float*)d_in[18];
    const float* bc   = (const float*)d_in[19];
    float* out = (float*)d_out;

    int IN = in_sizes[2] / HC_;       // 128
    int N  = in_sizes[0] / IN;        // 50000
    int E  = in_sizes[1] / 2;         // 800000
    int Etot = E + N;

    void *p_xl, *p_xr, *p_h, *p_acc, *p_nmax, *p_den;
    cudaGetSymbolAddress(&p_xl,  g_xl);
    cudaGetSymbolAddress(&p_xr,  g_xr);
    cudaGetSymbolAddress(&p_h,   g_h);
    cudaGetSymbolAddress(&p_acc, g_acc);
    cudaGetSymbolAddress(&p_nmax, g_nmax);
    cudaGetSymbolAddress(&p_den,  g_den);

    // edge index conversion (int64 vs int32 detection, done on device)
    k_detect<<<1, 1>>>((const int*)ei, E);
    k_convert<<<(2 * E + 255) / 256, 256>>>(ei, E);

    dim3 ggrid(HC_ / 64, (N + 63) / 64);
    int edgeWarpBlocks = (Etot * 32 + 255) / 256;
    int edgeThrBlocks  = (Etot + 255) / 256;

    // ---------------- layer 0 ----------------
    sgemm64<<<ggrid, 256>>>(x, Wl0, (float*)p_xl, N, IN, HC_);
    sgemm64<<<ggrid, 256>>>(x, Wr0, (float*)p_xr, N, IN, HC_);
    cudaMemsetAsync(p_nmax, 0, (size_t)N * H_ * sizeof(unsigned), 0);
    cudaMemsetAsync(p_den,  0, (size_t)N * H_ * sizeof(float), 0);
    cudaMemsetAsync(p_acc,  0, (size_t)N * HC_ * sizeof(float), 0);
    edge_logits_max<<<edgeWarpBlocks, 256>>>(att0, E, N);
    edge_exp_sum<<<edgeThrBlocks, 256>>>(E, N);
    edge_aggregate<<<edgeWarpBlocks, 256>>>(E, N);
    node_post0<<<(unsigned)(((long long)N * HC_ + 255) / 256), 256>>>(b0, g0, be0, m0, v0, N);

    // ---------------- layer 1 ----------------
    sgemm64<<<ggrid, 256>>>((const float*)p_h, Wl1, (float*)p_xl, N, HC_, HC_);
    sgemm64<<<ggrid, 256>>>((const float*)p_h, Wr1, (float*)p_xr, N, HC_, HC_);
    cudaMemsetAsync(p_nmax, 0, (size_t)N * H_ * sizeof(unsigned), 0);
    cudaMemsetAsync(p_den,  0, (size_t)N * H_ * sizeof(float), 0);
    cudaMemsetAsync(p_acc,  0, (size_t)N * HC_ * sizeof(float), 0);
    edge_logits_max<<<edgeWarpBlocks, 256>>>(att1, E, N);
    edge_exp_sum<<<edgeThrBlocks, 256>>>(E, N);
    edge_aggregate<<<edgeWarpBlocks, 256>>>(E, N);
    node_post1<<<(N * 32 + 255) / 256, 256>>>(b1, g1, be1, m1, v1, Wc, bc, out, N);
}

// round 6
// speedup vs baseline: 1.8192x; 1.8192x over previous
#include <cuda_runtime.h>
#include <cuda_bf16.h>

// ---------------------------------------------------------------------------
// GATv2 (2 layers) + BN + ELU + linear classifier.
// Shapes fixed by the problem: N=50000, E=800000, IN=128, H=8, C=32, NC=2.
// Strategy: CSR-sorted edges (built once per launch), warp-per-node fused
// attention+epilogue kernels (no atomics), 128x128 vectorized-LDS SGEMM.
// ---------------------------------------------------------------------------

#define NMAX 50000
#define EMAX 800000
#define H_ 8
#define C_ 32
#define HC_ 256       // H*C
#define ETOTMAX (EMAX + NMAX)
#define EPS_ 1e-5f
#define SLOPE_ 0.2f

// ------------------------- static device scratch ---------------------------
__device__ float g_xl[(size_t)NMAX * HC_];
__device__ float g_xr[(size_t)NMAX * HC_];
__device__ float g_h [(size_t)NMAX * HC_];
__device__ float g_elog[(size_t)ETOTMAX * H_];
__device__ int   g_src[EMAX];
__device__ int   g_dst[EMAX];
__device__ int   g_off[NMAX + 1];
__device__ int   g_cnt[NMAX];        // counts, then cursor
__device__ int   g_esrc[ETOTMAX];    // CSR: src node per edge slot
__device__ int   g_is64;

// ------------------------- edge index conversion ----------------------------
__global__ void k_detect(const int* __restrict__ ei, int E) {
    int ok64 = 1;
    int limit = (E > 64) ? 64 : E;
    for (int i = 0; i < limit; i++) {
        if (ei[2 * i + 1] != 0) { ok64 = 0; break; }
    }
    g_is64 = ok64;
}

__global__ void k_convert(const void* __restrict__ ei, int E) {
    int i = blockIdx.x * blockDim.x + threadIdx.x;
    int tot = 2 * E;
    if (i >= tot) return;
    int v;
    if (g_is64) v = (int)((const long long*)ei)[i];
    else        v = ((const int*)ei)[i];
    if (i < E) g_src[i] = v;
    else       g_dst[i - E] = v;
}

// ------------------------- CSR build ----------------------------------------
__global__ void k_hist(int E, int N) {
    int i = blockIdx.x * blockDim.x + threadIdx.x;
    if (i < E)          atomicAdd(&g_cnt[g_dst[i]], 1);
    else if (i < E + N) atomicAdd(&g_cnt[i - E], 1);   // self loop
}

// single block, 1024 threads: sequential chunked inclusive scan
__global__ void k_scan(int N) {
    __shared__ int buf[1024];
    __shared__ int carry_s;
    if (threadIdx.x == 0) carry_s = 0;
    __syncthreads();
    for (int base = 0; base < N; base += 1024) {
        int i = base + threadIdx.x;
        int v = (i < N) ? g_cnt[i] : 0;
        buf[threadIdx.x] = v;
        __syncthreads();
#pragma unroll
        for (int off = 1; off < 1024; off <<= 1) {
            int t = (threadIdx.x >= off) ? buf[threadIdx.x - off] : 0;
            __syncthreads();
            buf[threadIdx.x] += t;
            __syncthreads();
        }
        int incl = buf[threadIdx.x] + carry_s;
        if (i < N) {
            g_off[i + 1] = incl;
            g_cnt[i] = incl - v;   // cursor = exclusive prefix
        }
        __syncthreads();
        if (threadIdx.x == 1023) carry_s = incl;
        __syncthreads();
    }
    if (threadIdx.x == 0) g_off[0] = 0;
}

__global__ void k_scatter(int E, int N) {
    int i = blockIdx.x * blockDim.x + threadIdx.x;
    if (i < E) {
        int pos = atomicAdd(&g_cnt[g_dst[i]], 1);
        g_esrc[pos] = g_src[i];
    } else if (i < E + N) {
        int n = i - E;
        int pos = atomicAdd(&g_cnt[n], 1);
        g_esrc[pos] = n;
    }
}

// ------------------------- SGEMM: C[M,Nn] = A[M,K] @ B[K,Nn] ----------------
// 128x128 tile, 8x8 microtile, 256 threads, K-step 16, vectorized LDS.
__global__ void __launch_bounds__(256, 2)
sgemm128(const float* __restrict__ A, const float* __restrict__ B,
         float* __restrict__ Cc, int M, int K, int Nn) {
    __shared__ float As[16][132];
    __shared__ float Bs[16][128];
    int t  = threadIdx.x;
    int tx = t & 15, ty = t >> 4;
    int row0 = blockIdx.y * 128, col0 = blockIdx.x * 128;
    float acc[8][8] = {};
    for (int k0 = 0; k0 < K; k0 += 16) {
#pragma unroll
        for (int i = 0; i < 2; i++) {
            int idx = t * 2 + i;          // 0..511
            int m = idx >> 2, kq = idx & 3;
            int gr = row0 + m;
            float4 v = make_float4(0.f, 0.f, 0.f, 0.f);
            if (gr < M) v = *(const float4*)(A + (long long)gr * K + k0 + kq * 4);
            As[kq * 4 + 0][m] = v.x;
            As[kq * 4 + 1][m] = v.y;
            As[kq * 4 + 2][m] = v.z;
            As[kq * 4 + 3][m] = v.w;
        }
#pragma unroll
        for (int i = 0; i < 2; i++) {
            int idx = t * 2 + i;
            int kk = idx >> 5, n4 = idx & 31;
            *(float4*)&Bs[kk][n4 * 4] =
                *(const float4*)(B + (long long)(k0 + kk) * Nn + col0 + n4 * 4);
        }
        __syncthreads();
#pragma unroll
        for (int kk = 0; kk < 16; kk++) {
            float a[8], b[8];
            *(float4*)(a)     = *(float4*)&As[kk][ty * 8];
            *(float4*)(a + 4) = *(float4*)&As[kk][ty * 8 + 4];
            *(float4*)(b)     = *(float4*)&Bs[kk][tx * 8];
            *(float4*)(b + 4) = *(float4*)&Bs[kk][tx * 8 + 4];
#pragma unroll
            for (int i = 0; i < 8; i++)
#pragma unroll
                for (int j = 0; j < 8; j++) acc[i][j] += a[i] * b[j];
        }
        __syncthreads();
    }
#pragma unroll
    for (int i = 0; i < 8; i++) {
        int gr = row0 + ty * 8 + i;
        if (gr < M) {
            float* cp = Cc + (long long)gr * Nn + col0 + tx * 8;
            *(float4*)(cp)     = *(float4*)&acc[i][0];
            *(float4*)(cp + 4) = *(float4*)&acc[i][4];
        }
    }
}

// ------------------------- fused per-node attention --------------------------
// Warp per destination node. Two loops over incoming (CSR) edges:
//  1) logits (leakyrelu dot att), running max, store logits
//  2) exp, denom, weighted aggregate in registers
// Then the layer-specific epilogue. No atomics anywhere.
__device__ __forceinline__ void gat_core(int n, int lane, const float4* att4,
                                         float4& o0, float4& o1) {
    int beg = g_off[n], end = g_off[n + 1];
    int h0 = lane >> 3;
    const float4* xr4 = (const float4*)(g_xr + (long long)n * HC_);
    float4 r0 = xr4[lane], r1 = xr4[lane + 32];
    float4 a0 = att4[lane], a1 = att4[lane + 32];
    float mx0 = -3.4e38f, mx1 = -3.4e38f;
    for (int i = beg; i < end; i++) {
        int s = g_esrc[i];
        const float4* xl4 = (const float4*)(g_xl + (long long)s * HC_);
        float4 l0 = xl4[lane], l1 = xl4[lane + 32];
        float v, s0 = 0.f, s1 = 0.f;
        v = l0.x + r0.x; v = (v > 0.f) ? v : SLOPE_ * v; s0 += v * a0.x;
        v = l0.y + r0.y; v = (v > 0.f) ? v : SLOPE_ * v; s0 += v * a0.y;
        v = l0.z + r0.z; v = (v > 0.f) ? v : SLOPE_ * v; s0 += v * a0.z;
        v = l0.w + r0.w; v = (v > 0.f) ? v : SLOPE_ * v; s0 += v * a0.w;
        v = l1.x + r1.x; v = (v > 0.f) ? v : SLOPE_ * v; s1 += v * a1.x;
        v = l1.y + r1.y; v = (v > 0.f) ? v : SLOPE_ * v; s1 += v * a1.y;
        v = l1.z + r1.z; v = (v > 0.f) ? v : SLOPE_ * v; s1 += v * a1.z;
        v = l1.w + r1.w; v = (v > 0.f) ? v : SLOPE_ * v; s1 += v * a1.w;
#pragma unroll
        for (int off = 4; off; off >>= 1) {
            s0 += __shfl_xor_sync(0xffffffffu, s0, off);
            s1 += __shfl_xor_sync(0xffffffffu, s1, off);
        }
        mx0 = fmaxf(mx0, s0);
        mx1 = fmaxf(mx1, s1);
        if ((lane & 7) == 0) {
            g_elog[(long long)i * H_ + h0]     = s0;
            g_elog[(long long)i * H_ + h0 + 4] = s1;
        }
    }
    float den0 = 0.f, den1 = 0.f;
    float4 ac0 = make_float4(0.f, 0.f, 0.f, 0.f);
    float4 ac1 = make_float4(0.f, 0.f, 0.f, 0.f);
    for (int i = beg; i < end; i++) {
        int s = g_esrc[i];
        float lg0 = g_elog[(long long)i * H_ + h0];
        float lg1 = g_elog[(long long)i * H_ + h0 + 4];
        float ex0 = __expf(lg0 - mx0);
        float ex1 = __expf(lg1 - mx1);
        den0 += ex0; den1 += ex1;
        const float4* xl4 = (const float4*)(g_xl + (long long)s * HC_);
        float4 l0 = xl4[lane], l1 = xl4[lane + 32];
        ac0.x += ex0 * l0.x; ac0.y += ex0 * l0.y;
        ac0.z += ex0 * l0.z; ac0.w += ex0 * l0.w;
        ac1.x += ex1 * l1.x; ac1.y += ex1 * l1.y;
        ac1.z += ex1 * l1.z; ac1.w += ex1 * l1.w;
    }
    float i0 = 1.f / den0, i1 = 1.f / den1;
    o0 = make_float4(ac0.x * i0, ac0.y * i0, ac0.z * i0, ac0.w * i0);
    o1 = make_float4(ac1.x * i1, ac1.y * i1, ac1.z * i1, ac1.w * i1);
}

// layer 0: h = elu(bn(out + b0)), concat layout [N, 256]
__global__ void gat_layer0(const float* __restrict__ att,
                           const float* __restrict__ b0, const float* __restrict__ g0,
                           const float* __restrict__ be0, const float* __restrict__ m0,
                           const float* __restrict__ v0, int N) {
    int lane = threadIdx.x & 31;
    int n = (blockIdx.x * blockDim.x + threadIdx.x) >> 5;
    if (n >= N) return;
    float4 o0, o1;
    gat_core(n, lane, (const float4*)att, o0, o1);
    float4* ph = (float4*)(g_h + (long long)n * HC_);
    float out[8] = {o0.x, o0.y, o0.z, o0.w, o1.x, o1.y, o1.z, o1.w};
#pragma unroll
    for (int half = 0; half < 2; half++) {
        int q = lane + half * 32;
        float4 bb = ((const float4*)b0)[q];
        float4 gg = ((const float4*)g0)[q];
        float4 be = ((const float4*)be0)[q];
        float4 mm = ((const float4*)m0)[q];
        float4 vv = ((const float4*)v0)[q];
        float r[4];
        float xb[4] = {out[half*4+0] + bb.x, out[half*4+1] + bb.y,
                       out[half*4+2] + bb.z, out[half*4+3] + bb.w};
        float mu[4] = {mm.x, mm.y, mm.z, mm.w};
        float va[4] = {vv.x, vv.y, vv.z, vv.w};
        float ga[4] = {gg.x, gg.y, gg.z, gg.w};
        float ba[4] = {be.x, be.y, be.z, be.w};
#pragma unroll
        for (int j = 0; j < 4; j++) {
            float xv = (xb[j] - mu[j]) * rsqrtf(va[j] + EPS_) * ga[j] + ba[j];
            r[j] = (xv > 0.f) ? xv : (__expf(xv) - 1.f);
        }
        ph[q] = make_float4(r[0], r[1], r[2], r[3]);
    }
}

// layer 1: s = bn(mean_h(out) + b1); y = s @ Wc + bc  -> out [N, 2]
__global__ void gat_layer1(const float* __restrict__ att,
                           const float* __restrict__ b1, const float* __restrict__ g1,
                           const float* __restrict__ be1, const float* __restrict__ m1,
                           const float* __restrict__ v1, const float* __restrict__ Wc,
                           const float* __restrict__ bc, float* __restrict__ outp, int N) {
    int lane = threadIdx.x & 31;
    int n = (blockIdx.x * blockDim.x + threadIdx.x) >> 5;
    if (n >= N) return;
    float4 o0, o1;
    gat_core(n, lane, (const float4*)att, o0, o1);
    // sum over 8 heads: o0 covers head lane>>3, o1 head (lane>>3)+4, channels (lane&7)*4..+3
    float t0 = o0.x + o1.x, t1 = o0.y + o1.y, t2 = o0.z + o1.z, t3 = o0.w + o1.w;
#pragma unroll
    for (int off = 8; off <= 16; off <<= 1) {
        t0 += __shfl_xor_sync(0xffffffffu, t0, off);
        t1 += __shfl_xor_sync(0xffffffffu, t1, off);
        t2 += __shfl_xor_sync(0xffffffffu, t2, off);
        t3 += __shfl_xor_sync(0xffffffffu, t3, off);
    }
    int cg = lane & 7;      // channel group: channels cg*4..cg*4+3
    float4 bb = ((const float4*)b1)[cg];
    float4 gg = ((const float4*)g1)[cg];
    float4 be = ((const float4*)be1)[cg];
    float4 mm = ((const float4*)m1)[cg];
    float4 vv = ((const float4*)v1)[cg];
    float s0 = (t0 * 0.125f + bb.x - mm.x) * rsqrtf(vv.x + EPS_) * gg.x + be.x;
    float s1 = (t1 * 0.125f + bb.y - mm.y) * rsqrtf(vv.y + EPS_) * gg.y + be.y;
    float s2 = (t2 * 0.125f + bb.z - mm.z) * rsqrtf(vv.z + EPS_) * gg.z + be.z;
    float s3 = (t3 * 0.125f + bb.w - mm.w) * rsqrtf(vv.w + EPS_) * gg.w + be.w;
    int c0 = cg * 4;
    float y0 = s0 * Wc[(c0+0)*2] + s1 * Wc[(c0+1)*2] + s2 * Wc[(c0+2)*2] + s3 * Wc[(c0+3)*2];
    float y1 = s0 * Wc[(c0+0)*2+1] + s1 * Wc[(c0+1)*2+1] + s2 * Wc[(c0+2)*2+1] + s3 * Wc[(c0+3)*2+1];
#pragma unroll
    for (int off = 4; off; off >>= 1) {
        y0 += __shfl_xor_sync(0xffffffffu, y0, off);
        y1 += __shfl_xor_sync(0xffffffffu, y1, off);
    }
    if (lane == 0) {
        outp[(long long)n * 2 + 0] = y0 + bc[0];
        outp[(long long)n * 2 + 1] = y1 + bc[1];
    }
}

// ---------------------------------------------------------------------------
extern "C" void kernel_launch(void* const* d_in, const int* in_sizes, int n_in,
                              void* d_out, int out_size) {
    const float* x    = (const float*)d_in[0];
    const void*  ei   = d_in[1];
    const float* Wl0  = (const float*)d_in[2];
    const float* Wr0  = (const float*)d_in[3];
    const float* att0 = (const float*)d_in[4];
    const float* b0   = (const float*)d_in[5];
    const float* g0   = (const float*)d_in[6];
    const float* be0  = (const float*)d_in[7];
    const float* m0   = (const float*)d_in[8];
    const float* v0   = (const float*)d_in[9];
    const float* Wl1  = (const float*)d_in[10];
    const float* Wr1  = (const float*)d_in[11];
    const float* att1 = (const float*)d_in[12];
    const float* b1   = (const float*)d_in[13];
    const float* g1   = (const float*)d_in[14];
    const float* be1  = (const float*)d_in[15];
    const float* m1   = (const float*)d_in[16];
    const float* v1   = (const float*)d_in[17];
    const float* Wc   = (const float*)d_in[18];
    const float* bc   = (const float*)d_in[19];
    float* out = (float*)d_out;

    int IN = in_sizes[2] / HC_;       // 128
    int N  = in_sizes[0] / IN;        // 50000
    int E  = in_sizes[1] / 2;         // 800000
    int Etot = E + N;

    void *p_xl, *p_xr, *p_h, *p_cnt;
    cudaGetSymbolAddress(&p_xl,  g_xl);
    cudaGetSymbolAddress(&p_xr,  g_xr);
    cudaGetSymbolAddress(&p_h,   g_h);
    cudaGetSymbolAddress(&p_cnt, g_cnt);

    // ---- edge index conversion + CSR build (once; reused by both layers) ----
    k_detect<<<1, 1>>>((const int*)ei, E);
    k_convert<<<(2 * E + 255) / 256, 256>>>(ei, E);
    cudaMemsetAsync(p_cnt, 0, (size_t)N * sizeof(int), 0);
    k_hist<<<(Etot + 255) / 256, 256>>>(E, N);
    k_scan<<<1, 1024>>>(N);
    k_scatter<<<(Etot + 255) / 256, 256>>>(E, N);

    dim3 ggrid(HC_ / 128, (N + 127) / 128);
    int nodeBlocks = (N * 32 + 255) / 256;

    // ---------------- layer 0 ----------------
    sgemm128<<<ggrid, 256>>>(x, Wl0, (float*)p_xl, N, IN, HC_);
    sgemm128<<<ggrid, 256>>>(x, Wr0, (float*)p_xr, N, IN, HC_);
    gat_layer0<<<nodeBlocks, 256>>>(att0, b0, g0, be0, m0, v0, N);

    // ---------------- layer 1 ----------------
    sgemm128<<<ggrid, 256>>>((const float*)p_h, Wl1, (float*)p_xl, N, HC_, HC_);
    sgemm128<<<ggrid, 256>>>((const float*)p_h, Wr1, (float*)p_xr, N, HC_, HC_);
    gat_layer1<<<nodeBlocks, 256>>>(att1, b1, g1, be1, m1, v1, Wc, bc, out, N);
}